// round 12
// baseline (speedup 1.0000x reference)
#include <cuda_runtime.h>

// Problem sizes (fixed by the reference)
#define BB 32
#define TT 512
#define EE 1024
#define HH 1024

// ---------------------------------------------------------------------------
// f32x2 packed-FMA helpers (sm_103a FFMA2 path; ptxas only emits via PTX)
// ---------------------------------------------------------------------------
static __device__ __forceinline__ void fma2(unsigned long long &acc,
                                            unsigned long long a,
                                            unsigned long long b) {
    asm("fma.rn.f32x2 %0, %1, %2, %0;" : "+l"(acc) : "l"(a), "l"(b));
}
static __device__ __forceinline__ float2 unpk(unsigned long long v) {
    float2 r;
    asm("mov.b64 {%0, %1}, %2;" : "=f"(r.x), "=f"(r.y) : "l"(v));
    return r;
}
static __device__ __forceinline__ unsigned ld_rlx(const unsigned* p) {
    unsigned v;
    asm volatile("ld.relaxed.gpu.global.u32 %0, [%1];" : "=r"(v) : "l"(p));
    return v;
}
static __device__ __forceinline__ void fence_acq() {
    asm volatile("fence.acq_rel.gpu;" ::: "memory");
}
static __device__ __forceinline__ void st_rel(unsigned* p, unsigned v) {
    asm volatile("st.release.gpu.global.u32 [%0], %1;" :: "l"(p), "r"(v) : "memory");
}
static __device__ __forceinline__ float tanh_fast(float x) {
    float y;
    asm("tanh.approx.f32 %0, %1;" : "=f"(y) : "f"(x));
    return y;
}

// ---------------------------------------------------------------------------
// Global scratch: 3-deep hidden-state ring + per-CTA monotonic step flags
// ---------------------------------------------------------------------------
__device__ float    g_h[3][BB * HH];
__device__ unsigned g_flag[128 * 32];       // one flag per CTA, 128B stride

// ---------------------------------------------------------------------------
// Phase 1: out[m][n] = sum_k X[m][k] * W[n][k] + (bih[n] + bhh[n])
// M=16384, N=1024, K=1024, NT GEMM, FFMA2, 128x64 tile, double-buffered smem.
// Block (0,0) additionally zeroes g_h[0] and the flags (init merged here).
// ---------------------------------------------------------------------------
#define BM  128
#define BN  64
#define BK  32
#define LDA 36

__global__ __launch_bounds__(256) void gemm_xp_kernel(
    const float* __restrict__ X, const float* __restrict__ W,
    const float* __restrict__ bih, const float* __restrict__ bhh,
    float* __restrict__ out)
{
    __shared__ __align__(16) float As[2][BM * LDA];
    __shared__ __align__(16) float Bs[2][BN * LDA];

    const int tid = threadIdx.x;
    const int m0  = blockIdx.y * BM;
    const int n0  = blockIdx.x * BN;
    const int r   = tid & 15;
    const int c   = tid >> 4;

    // ---- merged init (block (0,0) only): zero h_0 ring slot + flags ------
    if (blockIdx.x == 0 && blockIdx.y == 0) {
        float4 z4 = make_float4(0.f, 0.f, 0.f, 0.f);
#pragma unroll
        for (int u = 0; u < 32; u++)                    // 32K floats = 8K f4
            *((float4*)g_h[0] + tid + u * 256) = z4;
#pragma unroll
        for (int u = 0; u < 16; u++)                    // 4096 flags
            g_flag[tid + u * 256] = 0u;
    }

    // staging coordinates (same for every tile)
    const int srow = tid >> 3;
    const int skk  = (tid & 7) << 2;

    unsigned long long acc[8][4];
#pragma unroll
    for (int i = 0; i < 8; i++)
#pragma unroll
        for (int j = 0; j < 4; j++) acc[i][j] = 0ull;

    // Preload tile 0
#pragma unroll
    for (int u = 0; u < 4; u++)
        *(float4*)&As[0][(srow + u * 32) * LDA + skk] =
            *(const float4*)&X[(m0 + srow + u * 32) * EE + skk];
#pragma unroll
    for (int u = 0; u < 2; u++)
        *(float4*)&Bs[0][(srow + u * 32) * LDA + skk] =
            *(const float4*)&W[(n0 + srow + u * 32) * EE + skk];
    __syncthreads();

    int cur = 0;
    for (int kt = 0; kt < EE; kt += BK) {
        float4 pa[4], pb[2];
        if (kt + BK < EE) {
#pragma unroll
            for (int u = 0; u < 4; u++)
                pa[u] = *(const float4*)&X[(m0 + srow + u * 32) * EE + kt + BK + skk];
#pragma unroll
            for (int u = 0; u < 2; u++)
                pb[u] = *(const float4*)&W[(n0 + srow + u * 32) * EE + kt + BK + skk];
        }

#pragma unroll
        for (int kk = 0; kk < BK; kk += 4) {
            ulonglong2 av[8];
            ulonglong2 bv[4];
#pragma unroll
            for (int i = 0; i < 8; i++)
                av[i] = *(const ulonglong2*)&As[cur][(r + 16 * i) * LDA + kk];
#pragma unroll
            for (int j = 0; j < 4; j++)
                bv[j] = *(const ulonglong2*)&Bs[cur][(c + 16 * j) * LDA + kk];
#pragma unroll
            for (int i = 0; i < 8; i++) {
#pragma unroll
                for (int j = 0; j < 4; j++) {
                    fma2(acc[i][j], av[i].x, bv[j].x);
                    fma2(acc[i][j], av[i].y, bv[j].y);
                }
            }
        }

        if (kt + BK < EE) {
#pragma unroll
            for (int u = 0; u < 4; u++)
                *(float4*)&As[1 - cur][(srow + u * 32) * LDA + skk] = pa[u];
#pragma unroll
            for (int u = 0; u < 2; u++)
                *(float4*)&Bs[1 - cur][(srow + u * 32) * LDA + skk] = pb[u];
        }
        __syncthreads();
        cur ^= 1;
    }

#pragma unroll
    for (int j = 0; j < 4; j++) {
        int n = n0 + c + 16 * j;
        float bias = bih[n] + bhh[n];
#pragma unroll
        for (int i = 0; i < 8; i++) {
            float2 v = unpk(acc[i][j]);
            out[(m0 + r + 16 * i) * HH + n] = v.x + v.y + bias;
        }
    }
}

// ---------------------------------------------------------------------------
// Phase 2: persistent recurrence. 128 CTAs (co-resident), 256 threads.
//   CTA = batch group gb (8 batches) x col block cb (32 cols), full K = 1024.
//   Thread (ks = tid>>2 in 0..63, c8 = tid&3) computes an
//   8 batch x 8 col x Kt=16 FFMA2 partial; KS=64 partials reduced via a
//   64 KB smem tile. Conflict-free swizzles as derived in R9 (verified by
//   the L1-pipe drop 55% -> ~36-50%).
//
//   Sync: per-CTA monotonic flag. Producer: __stcg h (L2 write-through),
//   __syncthreads, st.release flag. Consumer: RELAXED poll + one
//   fence.acq_rel.gpu on detection (acquire-per-poll removed), then stage
//   via __ldcg. 3-deep ring absorbs the <=1-step skew.
// ---------------------------------------------------------------------------
#define RGRID   128
#define RW_FLT  (32 * 1024)   // W slice, swizzled     (128 KB)
#define RH_FLT  (8 * 1024)    // h slice               ( 32 KB)
#define RR_FLT  (64 * 256)    // reduction partials    ( 64 KB)
#define RSM_BYTES ((RW_FLT + RH_FLT + RR_FLT) * 4)

__global__ __launch_bounds__(256, 1) void rnn_rec_kernel(
    const float* __restrict__ Whh, float* __restrict__ out)
{
    extern __shared__ __align__(16) float sm[];
    float* Ws  = sm;                     // [32 cols][1024] swizzled
    float* hs  = sm + RW_FLT;            // [8 batches][1024]
    float* red = sm + RW_FLT + RH_FLT;   // [64 ks][256 outputs]

    const int tid = threadIdx.x;
    const int gb  = blockIdx.x >> 5;          // batch group 0..3
    const int c0  = (blockIdx.x & 31) * 32;   // global col base
    const int ks  = tid >> 2;                 // k chunk 0..63 (16 floats)
    const int c8  = tid & 3;                  // col oct 0..3

    // ---- Stage W slice (once), low-2 swizzle keyed on col oct ------------
#pragma unroll 4
    for (int u = 0; u < 32; u++) {
        int f   = tid + u * 256;          // float4 index 0..8191
        int col = f >> 8;                 // local col 0..31
        int g   = f & 255;                // granule
        int gp  = (g & ~3) | ((g ^ (col >> 3)) & 3);
        float4 v = *(const float4*)&Whh[(c0 + col) * HH + g * 4];
        *(float4*)&Ws[col * 1024 + gp * 4] = v;
    }

    // Per-thread invariant pointers
    const float* wbase = &Ws[(c8 * 8) * 1024 + ks * 16];
    const float* hbase = &hs[ks * 16];

    // Producer of this thread's k chunk: CTA (gb, ks>>1) (32 cols/CTA)
    const unsigned* my_src_flag = &g_flag[(gb * 32 + (ks >> 1)) * 32];
    unsigned*       my_flag     = &g_flag[blockIdx.x * 32];

    // Staging: thread copies granule column (4*ks + c8) across 8 rows
    const int g_st = ks * 4 + c8;
    const unsigned grp_mask = 0xFu << (4 * (ks & 7));   // 4-lane group

    // Epilogue output mapping: o = tid = b*32 + colL (coalesced)
    const int b_out   = tid >> 5;
    const int colL    = tid & 31;
    const int oi_base = (gb * 8 + b_out) * TT * HH + (c0 + colL);
    const int hw_idx  = (gb * 8 + b_out) * HH + (c0 + colL);

    int cur = 0, nxt = 1, nnx = 2;        // rotating ring indices
    float xp_cur = __ldg(&out[oi_base]);  // prefetch xp for t = 0

    __syncthreads();   // Ws fully staged before first microloop

    for (int t = 0; t < TT; t++) {
        // ---- Wait for this chunk's producer: relaxed poll + one fence ----
        if (t) {
            while (ld_rlx(my_src_flag) < (unsigned)t) { }
            fence_acq();
        }
        // ---- Stage this granule column (8 rows) --------------------------
        {
            const float4* hsrc =
                (const float4*)(g_h[cur] + gb * 8 * HH) + g_st;
            float4* hdst = (float4*)&hs[g_st * 4];
#pragma unroll
            for (int u = 0; u < 8; u++)
                *(float4*)((char*)hdst + u * 4096) = __ldcg(hsrc + u * 256);
        }
        __syncwarp(grp_mask);

        // ---- 8x8 x Kt=16 FFMA2 microtile ---------------------------------
        unsigned long long acc[8][8];
#pragma unroll
        for (int i = 0; i < 8; i++)
#pragma unroll
            for (int j = 0; j < 8; j++) acc[i][j] = 0ull;

#pragma unroll
        for (int kq = 0; kq < 4; kq++) {
            ulonglong2 wv[8];
            const int wo = ((kq ^ c8) & 3) * 4;
#pragma unroll
            for (int j = 0; j < 8; j++)
                wv[j] = *(const ulonglong2*)(wbase + j * 1024 + wo);
#pragma unroll
            for (int i = 0; i < 8; i++) {
                ulonglong2 hv = *(const ulonglong2*)(hbase + i * 1024 + kq * 4);
#pragma unroll
                for (int j = 0; j < 8; j++) {
                    fma2(acc[i][j], hv.x, wv[j].x);
                    fma2(acc[i][j], hv.y, wv[j].y);
                }
            }
        }

        // ---- Reduce KS=64 partials through smem --------------------------
#pragma unroll
        for (int i = 0; i < 8; i++) {
            float2 a0 = unpk(acc[i][0]), a1 = unpk(acc[i][1]);
            float2 a2 = unpk(acc[i][2]), a3 = unpk(acc[i][3]);
            float2 a4 = unpk(acc[i][4]), a5 = unpk(acc[i][5]);
            float2 a6 = unpk(acc[i][6]), a7 = unpk(acc[i][7]);
            float4 v0, v1;
            v0.x = a0.x + a0.y; v0.y = a1.x + a1.y;
            v0.z = a2.x + a2.y; v0.w = a3.x + a3.y;
            v1.x = a4.x + a4.y; v1.y = a5.x + a5.y;
            v1.z = a6.x + a6.y; v1.w = a7.x + a7.y;
            *(float4*)&red[ks * 256 + i * 32 + c8 * 8]     = v0;
            *(float4*)&red[ks * 256 + i * 32 + c8 * 8 + 4] = v1;
        }
        __syncthreads();

        float p0 = 0.f, p1 = 0.f, p2 = 0.f, p3 = 0.f;
        float p4 = 0.f, p5 = 0.f, p6 = 0.f, p7 = 0.f;
#pragma unroll
        for (int k = 0; k < 64; k += 8) {
            p0 += red[(k + 0) * 256 + tid];
            p1 += red[(k + 1) * 256 + tid];
            p2 += red[(k + 2) * 256 + tid];
            p3 += red[(k + 3) * 256 + tid];
            p4 += red[(k + 4) * 256 + tid];
            p5 += red[(k + 5) * 256 + tid];
            p6 += red[(k + 6) * 256 + tid];
            p7 += red[(k + 7) * 256 + tid];
        }
        float s = ((p0 + p1) + (p2 + p3)) + ((p4 + p5) + (p6 + p7));

        // ---- tanh, publish h (L2 write-through), release flag ------------
        float hnew = tanh_fast(xp_cur + s);
        __stcg(&g_h[nxt][hw_idx], hnew);
        __syncthreads();                 // all h-writes of this CTA done
        if (tid == 0) st_rel(my_flag, (unsigned)(t + 1));

        // off the critical path:
        out[oi_base + t * HH] = hnew;
        if (t + 1 < TT) xp_cur = __ldg(&out[oi_base + (t + 1) * HH]);

        int tmp = cur; cur = nxt; nxt = nnx; nnx = tmp;
    }
}

// ---------------------------------------------------------------------------
// Launch: input-projection GEMM (+ merged init) -> recurrence  (2 launches)
// ---------------------------------------------------------------------------
extern "C" void kernel_launch(void* const* d_in, const int* in_sizes, int n_in,
                              void* d_out, int out_size)
{
    const float* x   = (const float*)d_in[0];
    const float* Wih = (const float*)d_in[1];
    const float* Whh = (const float*)d_in[2];
    const float* bih = (const float*)d_in[3];
    const float* bhh = (const float*)d_in[4];
    float* out = (float*)d_out;
    (void)in_sizes; (void)n_in; (void)out_size;

    cudaFuncSetAttribute(rnn_rec_kernel,
                         cudaFuncAttributeMaxDynamicSharedMemorySize,
                         RSM_BYTES);

    dim3 g1(HH / BN, (BB * TT) / BM);   // (16, 128)
    gemm_xp_kernel<<<g1, 256>>>(x, Wih, bih, bhh, out);

    rnn_rec_kernel<<<RGRID, 256, RSM_BYTES>>>(Whh, out);
}

// round 16
// speedup vs baseline: 1.0328x; 1.0328x over previous
#include <cuda_runtime.h>

// Problem sizes (fixed by the reference)
#define BB 32
#define TT 512
#define EE 1024
#define HH 1024

// ---------------------------------------------------------------------------
// f32x2 packed-FMA helpers (sm_103a FFMA2 path; ptxas only emits via PTX)
// ---------------------------------------------------------------------------
static __device__ __forceinline__ void fma2(unsigned long long &acc,
                                            unsigned long long a,
                                            unsigned long long b) {
    asm("fma.rn.f32x2 %0, %1, %2, %0;" : "+l"(acc) : "l"(a), "l"(b));
}
static __device__ __forceinline__ float2 unpk(unsigned long long v) {
    float2 r;
    asm("mov.b64 {%0, %1}, %2;" : "=f"(r.x), "=f"(r.y) : "l"(v));
    return r;
}
static __device__ __forceinline__ unsigned ld_acq(const unsigned* p) {
    unsigned v;
    asm volatile("ld.acquire.gpu.u32 %0, [%1];" : "=r"(v) : "l"(p));
    return v;
}
static __device__ __forceinline__ void st_rel(unsigned* p, unsigned v) {
    asm volatile("st.release.gpu.u32 [%0], %1;" :: "l"(p), "r"(v) : "memory");
}
static __device__ __forceinline__ float tanh_fast(float x) {
    float y;
    asm("tanh.approx.f32 %0, %1;" : "=f"(y) : "f"(x));
    return y;
}

// ---------------------------------------------------------------------------
// Global scratch: 3-deep hidden-state ring + per-CTA monotonic step flags
// ---------------------------------------------------------------------------
__device__ float    g_h[3][BB * HH];
__device__ unsigned g_flag[128 * 32];       // one flag per CTA, 128B stride

// ---------------------------------------------------------------------------
// Phase 1: out[m][n] = sum_k X[m][k] * W[n][k] + (bih[n] + bhh[n])
// M=16384, N=1024, K=1024, NT GEMM, FFMA2, 128x64 tile, double-buffered smem.
// Block (0,0) additionally zeroes g_h[0] and the flags (init merged here).
// ---------------------------------------------------------------------------
#define BM  128
#define BN  64
#define BK  32
#define LDA 36

__global__ __launch_bounds__(256) void gemm_xp_kernel(
    const float* __restrict__ X, const float* __restrict__ W,
    const float* __restrict__ bih, const float* __restrict__ bhh,
    float* __restrict__ out)
{
    __shared__ __align__(16) float As[2][BM * LDA];
    __shared__ __align__(16) float Bs[2][BN * LDA];

    const int tid = threadIdx.x;
    const int m0  = blockIdx.y * BM;
    const int n0  = blockIdx.x * BN;
    const int r   = tid & 15;
    const int c   = tid >> 4;

    // ---- merged init (block (0,0) only): zero h_0 ring slot + flags ------
    if (blockIdx.x == 0 && blockIdx.y == 0) {
        float4 z4 = make_float4(0.f, 0.f, 0.f, 0.f);
#pragma unroll
        for (int u = 0; u < 32; u++)                    // 32K floats = 8K f4
            *((float4*)g_h[0] + tid + u * 256) = z4;
#pragma unroll
        for (int u = 0; u < 16; u++)                    // 4096 flags
            g_flag[tid + u * 256] = 0u;
    }

    // staging coordinates (same for every tile)
    const int srow = tid >> 3;
    const int skk  = (tid & 7) << 2;

    unsigned long long acc[8][4];
#pragma unroll
    for (int i = 0; i < 8; i++)
#pragma unroll
        for (int j = 0; j < 4; j++) acc[i][j] = 0ull;

    // Preload tile 0
#pragma unroll
    for (int u = 0; u < 4; u++)
        *(float4*)&As[0][(srow + u * 32) * LDA + skk] =
            *(const float4*)&X[(m0 + srow + u * 32) * EE + skk];
#pragma unroll
    for (int u = 0; u < 2; u++)
        *(float4*)&Bs[0][(srow + u * 32) * LDA + skk] =
            *(const float4*)&W[(n0 + srow + u * 32) * EE + skk];
    __syncthreads();

    int cur = 0;
    for (int kt = 0; kt < EE; kt += BK) {
        float4 pa[4], pb[2];
        if (kt + BK < EE) {
#pragma unroll
            for (int u = 0; u < 4; u++)
                pa[u] = *(const float4*)&X[(m0 + srow + u * 32) * EE + kt + BK + skk];
#pragma unroll
            for (int u = 0; u < 2; u++)
                pb[u] = *(const float4*)&W[(n0 + srow + u * 32) * EE + kt + BK + skk];
        }

#pragma unroll
        for (int kk = 0; kk < BK; kk += 4) {
            ulonglong2 av[8];
            ulonglong2 bv[4];
#pragma unroll
            for (int i = 0; i < 8; i++)
                av[i] = *(const ulonglong2*)&As[cur][(r + 16 * i) * LDA + kk];
#pragma unroll
            for (int j = 0; j < 4; j++)
                bv[j] = *(const ulonglong2*)&Bs[cur][(c + 16 * j) * LDA + kk];
#pragma unroll
            for (int i = 0; i < 8; i++) {
#pragma unroll
                for (int j = 0; j < 4; j++) {
                    fma2(acc[i][j], av[i].x, bv[j].x);
                    fma2(acc[i][j], av[i].y, bv[j].y);
                }
            }
        }

        if (kt + BK < EE) {
#pragma unroll
            for (int u = 0; u < 4; u++)
                *(float4*)&As[1 - cur][(srow + u * 32) * LDA + skk] = pa[u];
#pragma unroll
            for (int u = 0; u < 2; u++)
                *(float4*)&Bs[1 - cur][(srow + u * 32) * LDA + skk] = pb[u];
        }
        __syncthreads();
        cur ^= 1;
    }

#pragma unroll
    for (int j = 0; j < 4; j++) {
        int n = n0 + c + 16 * j;
        float bias = bih[n] + bhh[n];
#pragma unroll
        for (int i = 0; i < 8; i++) {
            float2 v = unpk(acc[i][j]);
            out[(m0 + r + 16 * i) * HH + n] = v.x + v.y + bias;
        }
    }
}

// ---------------------------------------------------------------------------
// Phase 2: persistent recurrence. 128 CTAs x 512 THREADS (16 warps/SM =
//   4 warps/SMSP -> 2x the latency hiding of the 256-thread version; the
//   R9-measured profile was stall-bound: issue 20%, nothing saturated).
//
//   CTA = batch group gb (8 batches) x col block cb (32 cols), full K = 1024.
//   Thread (ks = tid>>3 in 0..63, c8 = tid&7) computes an
//   8 batch x 4 col (cols c8*4..+4) x Kt=16 FFMA2 partial; KS=64 partials
//   reduced in two half-K halves (scratch = dead hs buffer) then combined.
//
//   Warp geometry: warp = {ks in 4w..4w+3} x {c8 0..7}.
//   W store swizzle  g' = (g&~7) | ((g ^ (g>>3) ^ (col>>1)) & 7):
//     load term (4(ks&1)+kq) ^ (ks>>1) ^ (col>>1) -> enumerated uniform
//     4-per-bank-group over the 32 lanes  => conflict-free in min phases.
//   h store swizzle  g' = (g&~7) | ((g ^ 2*((g>>3)&1)) & 7):
//     4 unique addrs/warp in 4 distinct groups -> broadcast, 1 phase.
//   Sync: EXACT R9 protocol (per-thread ld.acquire spin, plain h store,
//   st.release flag) — the R10/R12 fence/stcg variants measured slower.
// ---------------------------------------------------------------------------
#define RGRID   128
#define RTHR    512
#define RW_FLT  (32 * 1024)   // W slice, swizzled     (128 KB)
#define RH_FLT  (8 * 1024)    // h slice, swizzled     ( 32 KB) + reduce scratch
#define RR_FLT  (64 * 256)    // reduction partials    ( 64 KB)
#define RSM_BYTES ((RW_FLT + RH_FLT + RR_FLT) * 4)

__global__ __launch_bounds__(RTHR, 1) void rnn_rec_kernel(
    const float* __restrict__ Whh, float* __restrict__ out)
{
    extern __shared__ __align__(16) float sm[];
    float* Ws  = sm;                     // [32 cols][1024] swizzled
    float* hs  = sm + RW_FLT;            // [8 batches][1024] swizzled
    float* red = sm + RW_FLT + RH_FLT;   // [64 ks][256 outputs]

    const int tid = threadIdx.x;
    const int gb  = blockIdx.x >> 5;          // batch group 0..3
    const int c0  = (blockIdx.x & 31) * 32;   // global col base
    const int ks  = tid >> 3;                 // k chunk 0..63 (16 floats)
    const int c8  = tid & 7;                  // col quad 0..7

    // ---- Stage W slice (once): 8192 float4, 16 per thread ----------------
#pragma unroll 4
    for (int u = 0; u < 16; u++) {
        int f   = tid + u * 512;          // float4 index 0..8191
        int col = f >> 8;                 // local col 0..31
        int g   = f & 255;                // granule
        int gp  = (g & ~7) | ((g ^ (g >> 3) ^ (col >> 1)) & 7);
        float4 v = *(const float4*)&Whh[(c0 + col) * HH + g * 4];
        *(float4*)&Ws[col * 1024 + gp * 4] = v;
    }

    // Per-thread invariant offsets
    const int sxh = 2 * ((ks >> 1) & 1);     // h swizzle term
    int sxw[4];
    const float* wcol[4];
#pragma unroll
    for (int j = 0; j < 4; j++) {
        int col = c8 * 4 + j;
        sxw[j]  = ((ks >> 1) ^ (col >> 1)) & 7;
        wcol[j] = &Ws[col * 1024];
    }

    // Producer of this thread's k chunk: CTA (gb, ks>>1) (32 cols/CTA)
    const unsigned* my_src_flag = &g_flag[(gb * 32 + (ks >> 1)) * 32];
    unsigned*       my_flag     = &g_flag[blockIdx.x * 32];

    // Staging: thread copies granule column gc = 4*ks + (c8&3),
    // rows rbase..rbase+3 where rbase = (c8>>2)*4  (4 granules per thread)
    const int gc    = ks * 4 + (c8 & 3);
    const int gp_st = (gc & ~7) | ((gc ^ sxh) & 7);
    const int rbase = (c8 >> 2) * 4;
    const unsigned grp_mask = 0xFFu << (8 * (ks & 3));   // 8-lane ks-group

    // Epilogue output mapping (threads 0..255): o = tid = b*32 + colL
    const int b_out   = tid >> 5;
    const int colL    = tid & 31;
    const bool epi    = (tid < 256);
    const int oi_base = epi ? (gb * 8 + b_out) * TT * HH + (c0 + colL) : 0;
    const int hw_idx  = epi ? (gb * 8 + b_out) * HH + (c0 + colL) : 0;

    // Reduce-half mapping: thread sums 32 of the 64 partial rows
    const int r_half = tid >> 8;          // 0 or 1
    const int r_out  = tid & 255;         // output index 0..255
    const int r_k0   = r_half * 32;

    int cur = 0, nxt = 1, nnx = 2;        // rotating ring indices
    float xp_cur = epi ? __ldg(&out[oi_base]) : 0.0f;   // xp for t = 0

    __syncthreads();   // Ws fully staged before first microloop

    for (int t = 0; t < TT; t++) {
        // ---- Wait for this chunk's producer (R9 acquire spin) ------------
        if (t) {
            while (ld_acq(my_src_flag) < (unsigned)t) { }
        }
        // ---- Stage 4 granules (rows rbase..rbase+3 of column gc) ---------
        {
            const float4* hsrc =
                (const float4*)(g_h[cur] + gb * 8 * HH) + gc;
            float4* hdst = (float4*)hs + gp_st;
#pragma unroll
            for (int u = 0; u < 4; u++) {
                int row = rbase + u;
                hdst[row * 256] = __ldcg(hsrc + row * 256);
            }
        }
        __syncwarp(grp_mask);

        // ---- 8x4 x Kt=16 FFMA2 microtile ---------------------------------
        unsigned long long acc[8][4];
#pragma unroll
        for (int i = 0; i < 8; i++)
#pragma unroll
            for (int j = 0; j < 4; j++) acc[i][j] = 0ull;

#pragma unroll
        for (int kq = 0; kq < 4; kq++) {
            const int g = 4 * ks + kq;
            ulonglong2 wv[4];
#pragma unroll
            for (int j = 0; j < 4; j++) {
                int gpw = (g & ~7) | ((g ^ sxw[j]) & 7);
                wv[j] = *(const ulonglong2*)(wcol[j] + gpw * 4);
            }
            const int gph = (g & ~7) | ((g ^ sxh) & 7);
#pragma unroll
            for (int i = 0; i < 8; i++) {
                ulonglong2 hv = *(const ulonglong2*)&hs[i * 1024 + gph * 4];
#pragma unroll
                for (int j = 0; j < 4; j++) {
                    fma2(acc[i][j], hv.x, wv[j].x);
                    fma2(acc[i][j], hv.y, wv[j].y);
                }
            }
        }

        // ---- Write KS=64 partials ----------------------------------------
#pragma unroll
        for (int i = 0; i < 8; i++) {
            float2 a0 = unpk(acc[i][0]), a1 = unpk(acc[i][1]);
            float2 a2 = unpk(acc[i][2]), a3 = unpk(acc[i][3]);
            float4 v;
            v.x = a0.x + a0.y; v.y = a1.x + a1.y;
            v.z = a2.x + a2.y; v.w = a3.x + a3.y;
            *(float4*)&red[ks * 256 + i * 32 + c8 * 4] = v;
        }
        __syncthreads();

        // ---- Reduce: each thread sums its 32-row half --------------------
        {
            float p0 = 0.f, p1 = 0.f, p2 = 0.f, p3 = 0.f;
#pragma unroll
            for (int k = 0; k < 32; k += 4) {
                p0 += red[(r_k0 + k + 0) * 256 + r_out];
                p1 += red[(r_k0 + k + 1) * 256 + r_out];
                p2 += red[(r_k0 + k + 2) * 256 + r_out];
                p3 += red[(r_k0 + k + 3) * 256 + r_out];
            }
            hs[tid] = (p0 + p1) + (p2 + p3);   // hs is dead here: scratch
        }
        __syncthreads();

        // ---- Combine halves, tanh, publish h, release flag ---------------
        if (epi) {
            float s = hs[tid] + hs[tid + 256];
            float hnew = tanh_fast(xp_cur + s);
            g_h[nxt][hw_idx] = hnew;
        }
        __syncthreads();                 // all h-writes of this CTA done
        if (tid == 0) st_rel(my_flag, (unsigned)(t + 1));

        // off the critical path:
        if (epi) {
            float hnew = g_h[nxt][hw_idx];
            out[oi_base + t * HH] = hnew;
            if (t + 1 < TT) xp_cur = __ldg(&out[oi_base + (t + 1) * HH]);
        }

        int tmp = cur; cur = nxt; nxt = nnx; nnx = tmp;
    }
}

// ---------------------------------------------------------------------------
// Launch: input-projection GEMM (+ merged init) -> recurrence  (2 launches)
// ---------------------------------------------------------------------------
extern "C" void kernel_launch(void* const* d_in, const int* in_sizes, int n_in,
                              void* d_out, int out_size)
{
    const float* x   = (const float*)d_in[0];
    const float* Wih = (const float*)d_in[1];
    const float* Whh = (const float*)d_in[2];
    const float* bih = (const float*)d_in[3];
    const float* bhh = (const float*)d_in[4];
    float* out = (float*)d_out;
    (void)in_sizes; (void)n_in; (void)out_size;

    cudaFuncSetAttribute(rnn_rec_kernel,
                         cudaFuncAttributeMaxDynamicSharedMemorySize,
                         RSM_BYTES);

    dim3 g1(HH / BN, (BB * TT) / BM);   // (16, 128)
    gemm_xp_kernel<<<g1, 256>>>(x, Wih, bih, bhh, out);

    rnn_rec_kernel<<<RGRID, RTHR, RSM_BYTES>>>(Whh, out);
}